// round 8
// baseline (speedup 1.0000x reference)
#include <cuda_runtime.h>
#include <cstdint>

// DCT_Layer: grouped conv, fixed separable 4x4 DCT basis, pad=2, min(|v|,8).
// x: (8,3,512,512) f32 -> out: (8,48,513,513) f32
//
// Block = 512 threads = 4 groups of 128; group kk owns planes kk*4+ll.
// 8 output rows per block (two 4-row halves), y0 % 8 == 0 so all store
// alignment shifts are compile-time. One 11-row staging phase per block.
//   A[0]={.5,.5,.5,.5}; A[1]={a,b,-b,-a}; A[2]={.5,-.5,-.5,.5}; A[3]={b,-a,a,-b}

#define HIN   512
#define WIN   512
#define HOUT  513
#define WOUT  513
#define PLANE (HOUT * WOUT)   // 263169 (== 1 mod 4)
#define XCOL  520             // s-cols 0..519; input col = s-col - 2
#define NROWS 11              // input rows y0-2 .. y0+8
#define CA 0.65328148243818826f
#define CB 0.27059805007309851f

#define SMEM_BYTES ((NROWS * XCOL + 4 * 4 * XCOL) * 4)   // 56,160 B

__device__ __forceinline__ float t8(float v) { return fminf(fabsf(v), 8.0f); }

// 4-tap row DCT of window w at offset c (compile-time after unroll)
template<int LL>
__device__ __forceinline__ float rowdct(const float* __restrict__ w, int c) {
    if (LL == 0) return 0.5f * ((w[c] + w[c+1]) + (w[c+2] + w[c+3]));
    if (LL == 1) return CA * (w[c] - w[c+3]) + CB * (w[c+1] - w[c+2]);
    if (LL == 2) return 0.5f * ((w[c] + w[c+3]) - (w[c+1] + w[c+2]));
    return CB * (w[c] - w[c+3]) - CA * (w[c+1] - w[c+2]);
}

// One plane row: aligned float4 store + edge columns.
// pl = plane base + y*513 + 4*tt; thread tt's window = s-cols 4tt..4tt+11.
template<int SH, int LL>
__device__ __forceinline__ void plane_out(const float* __restrict__ w,
                                          float* __restrict__ pl, int tt) {
    float4 v;
    v.x = t8(rowdct<LL>(w, SH + 0));
    v.y = t8(rowdct<LL>(w, SH + 1));
    v.z = t8(rowdct<LL>(w, SH + 2));
    v.w = t8(rowdct<LL>(w, SH + 3));
    if (SH <= 1 || tt < 127)
        *reinterpret_cast<float4*>(pl + SH) = v;

    if (SH > 0 && tt == 0) {                 // left edge cols 0..SH-1
#pragma unroll
        for (int c = 0; c < SH; c++)
            pl[c] = t8(rowdct<LL>(w, c));
    }
    constexpr int NP = (WOUT - SH) >> 2;
    constexpr int RS = SH + 4 * NP;
    if (RS < WOUT && tt == 127) {            // right edge cols RS..512
#pragma unroll
        for (int c = RS; c < WOUT; c++)
            pl[c - 508] = t8(rowdct<LL>(w, c - 508));
    }
}

// 4 planes of one kk for output row with (y % 4) == R
template<int R>
__device__ __forceinline__ void do_row(const float* __restrict__ w,
                                       float* __restrict__ pb, int tt) {
    plane_out<(4 - ((R + 0) & 3)) & 3, 0>(w, pb,                     tt);
    plane_out<(4 - ((R + 1) & 3)) & 3, 1>(w, pb + 1 * (size_t)PLANE, tt);
    plane_out<(4 - ((R + 2) & 3)) & 3, 2>(w, pb + 2 * (size_t)PLANE, tt);
    plane_out<(4 - ((R + 3) & 3)) & 3, 3>(w, pb + 3 * (size_t)PLANE, tt);
}

extern __shared__ float smem_dyn[];

__global__ __launch_bounds__(512, 4)
void dct_layer_kernel(const float* __restrict__ x, float* __restrict__ out) {
    const int y0 = blockIdx.x * 8;   // 0,8,...,512
    const int bc = blockIdx.y;       // 0..23
    const int t  = threadIdx.x;

    float (* __restrict__ xin)[XCOL] = reinterpret_cast<float(*)[XCOL]>(smem_dyn);
    float (* __restrict__ sc)[XCOL]  =
        reinterpret_cast<float(*)[XCOL]>(smem_dyn + NROWS * XCOL);  // [kk*4+r][c]

    const float* __restrict__ xp = x + (size_t)bc * (HIN * WIN);

    // ---- staging: 11 rows x 128 float4 (predicated LDG.128) + halo zeros
#pragma unroll
    for (int s = 0; s < 3; s++) {
        const int idx = t + s * 512;
        if (idx < NROWS * 128) {
            const int row = idx >> 7, j = idx & 127;
            const int iy = y0 - 2 + row;
            float4 v = make_float4(0.f, 0.f, 0.f, 0.f);
            if ((unsigned)iy < (unsigned)HIN)
                v = *reinterpret_cast<const float4*>(xp + iy * WIN + 4 * j);
            float* xr = &xin[row][2 + 4 * j];
            xr[0] = v.x; xr[1] = v.y; xr[2] = v.z; xr[3] = v.w;
        }
    }
    if (t < NROWS * 8) {   // halo cols 0,1,514..519 per row
        const int row = t >> 3, q = t & 7;
        xin[row][(q < 2) ? q : (512 + q)] = 0.f;
    }
    __syncthreads();

    const int kk = t >> 7, tt = t & 127;
    float* __restrict__ pb0 = out + (size_t)(bc * 16 + kk * 4) * PLANE
                                  + (size_t)y0 * WOUT + 4 * tt;

#pragma unroll
    for (int h = 0; h < 2; h++) {
        if (h == 1) {
            if (y0 + 4 >= HOUT) break;   // block-uniform
            __syncthreads();             // WAR: row pass(0) done before sc overwrite
        }

        // ---- cooperative column pass for rows y0+4h .. y0+4h+3
        for (int c = t; c < XCOL; c += 512) {
            float v0 = xin[4*h+0][c], v1 = xin[4*h+1][c], v2 = xin[4*h+2][c];
            float v3 = xin[4*h+3][c], v4 = xin[4*h+4][c], v5 = xin[4*h+5][c];
            float v6 = xin[4*h+6][c];
#pragma unroll
            for (int r = 0; r < 4; r++) {
                float a, b, d, e;
                switch (r) {
                    case 0: a = v0; b = v1; d = v2; e = v3; break;
                    case 1: a = v1; b = v2; d = v3; e = v4; break;
                    case 2: a = v2; b = v3; d = v4; e = v5; break;
                    default: a = v3; b = v4; d = v5; e = v6; break;
                }
                float p = a + e, q = b + d;
                float m = a - e, n = b - d;
                sc[0*4 + r][c] = 0.5f * (p + q);
                sc[1*4 + r][c] = CA * m + CB * n;
                sc[2*4 + r][c] = 0.5f * (p - q);
                sc[3*4 + r][c] = CB * m - CA * n;
            }
        }
        __syncthreads();

        // ---- row pass: group kk handles planes kk*4 .. kk*4+3
#pragma unroll
        for (int r = 0; r < 4; r++) {
            if (y0 + 4*h + r < HOUT) {
                float w[12];
                const float4* __restrict__ s4 =
                    reinterpret_cast<const float4*>(&sc[kk * 4 + r][0]);
                float4 a = s4[tt], b = s4[tt + 1], c2 = s4[tt + 2];
                w[0] = a.x;  w[1] = a.y;  w[2]  = a.z;  w[3]  = a.w;
                w[4] = b.x;  w[5] = b.y;  w[6]  = b.z;  w[7]  = b.w;
                w[8] = c2.x; w[9] = c2.y; w[10] = c2.z; w[11] = c2.w;

                float* __restrict__ pr = pb0 + (size_t)(4*h + r) * WOUT;
                switch (r) {            // r literal under unroll; y%4 == r
                    case 0: do_row<0>(w, pr, tt); break;
                    case 1: do_row<1>(w, pr, tt); break;
                    case 2: do_row<2>(w, pr, tt); break;
                    default: do_row<3>(w, pr, tt); break;
                }
            }
        }
    }
}

extern "C" void kernel_launch(void* const* d_in, const int* in_sizes, int n_in,
                              void* d_out, int out_size) {
    const float* x = (const float*)d_in[0];
    float* out     = (float*)d_out;
    (void)in_sizes; (void)n_in; (void)out_size;

    cudaFuncSetAttribute(dct_layer_kernel,
                         cudaFuncAttributeMaxDynamicSharedMemorySize, SMEM_BYTES);

    dim3 grid((HOUT + 7) / 8, 8 * 3);   // (65, 24)
    dim3 block(512);
    dct_layer_kernel<<<grid, block, SMEM_BYTES>>>(x, out);
}

// round 10
// speedup vs baseline: 1.0180x; 1.0180x over previous
#include <cuda_runtime.h>
#include <cstdint>

// DCT_Layer: grouped conv, fixed separable 4x4 DCT basis, pad=2, min(|v|,8).
// x: (8,3,512,512) f32 -> out: (8,48,513,513) f32
//
// Grid (129, 4, 24): rowgroup x kk x bc. Block = 512 = 4 ll-groups of 128.
// Block stages 7 input rows, column-DCTs for its kk, each ll-group writes
// plane kk*4+ll rows y0..y0+3 as one contiguous strip (aligned float4 + edges).
//   A[0]={.5,.5,.5,.5}; A[1]={a,b,-b,-a}; A[2]={.5,-.5,-.5,.5}; A[3]={b,-a,a,-b}

#define HIN   512
#define WIN   512
#define HOUT  513
#define WOUT  513
#define PLANE (HOUT * WOUT)   // 263169 (== 1 mod 4)
#define XCOL  520             // s-cols 0..519; input col = s-col - 2
#define CA 0.65328148243818826f
#define CB 0.27059805007309851f

__device__ __forceinline__ float t8(float v) { return fminf(fabsf(v), 8.0f); }

// 4-tap row DCT of window w at offset c (compile-time after unroll)
template<int LL>
__device__ __forceinline__ float rowdct(const float* __restrict__ w, int c) {
    if (LL == 0) return 0.5f * ((w[c] + w[c+1]) + (w[c+2] + w[c+3]));
    if (LL == 1) return CA * (w[c] - w[c+3]) + CB * (w[c+1] - w[c+2]);
    if (LL == 2) return 0.5f * ((w[c] + w[c+3]) - (w[c+1] + w[c+2]));
    return CB * (w[c] - w[c+3]) - CA * (w[c+1] - w[c+2]);
}

// One plane row: aligned float4 streaming store + edge columns.
// pl = plane base + y*513 + 4*tt; thread tt's window = s-cols 4tt..4tt+11.
template<int SH, int LL>
__device__ __forceinline__ void plane_out(const float* __restrict__ w,
                                          float* __restrict__ pl, int tt) {
    float4 v;
    v.x = t8(rowdct<LL>(w, SH + 0));
    v.y = t8(rowdct<LL>(w, SH + 1));
    v.z = t8(rowdct<LL>(w, SH + 2));
    v.w = t8(rowdct<LL>(w, SH + 3));
    if (SH <= 1 || tt < 127)
        __stcs(reinterpret_cast<float4*>(pl + SH), v);

    if (SH > 0 && tt == 0) {                 // left edge cols 0..SH-1
#pragma unroll
        for (int c = 0; c < SH; c++)
            pl[c] = t8(rowdct<LL>(w, c));
    }
    constexpr int NP = (WOUT - SH) >> 2;
    constexpr int RS = SH + 4 * NP;
    if (RS < WOUT && tt == 127) {            // right edge cols RS..512
#pragma unroll
        for (int c = RS; c < WOUT; c++)
            pl[c - 508] = t8(rowdct<LL>(w, c - 508));
    }
}

__shared__ float xin[7][XCOL];   // input rows y0-2 .. y0+4   (14,560 B)
__shared__ float sc[4][XCOL];    // column DCT (this kk) [r][c] (8,320 B)

// one output row R (compile-time) of plane LL; y0 % 4 == 0 -> y % 4 == R
template<int LL, int R>
__device__ __forceinline__ void row_out(float* __restrict__ pb, int tt) {
    float w[12];
    const float4* __restrict__ s4 = reinterpret_cast<const float4*>(&sc[R][0]);
    float4 a = s4[tt], b = s4[tt + 1], c2 = s4[tt + 2];
    w[0] = a.x;  w[1] = a.y;  w[2]  = a.z;  w[3]  = a.w;
    w[4] = b.x;  w[5] = b.y;  w[6]  = b.z;  w[7]  = b.w;
    w[8] = c2.x; w[9] = c2.y; w[10] = c2.z; w[11] = c2.w;
    plane_out<(4 - ((LL + R) & 3)) & 3, LL>(w, pb + (size_t)R * WOUT, tt);
}

// 4 rows of one plane (LL = this group's ll)
template<int LL>
__device__ __forceinline__ void tail_ll(float* __restrict__ pb, int tt, int nrow) {
    row_out<LL, 0>(pb, tt);
    if (nrow > 1) row_out<LL, 1>(pb, tt);
    if (nrow > 2) row_out<LL, 2>(pb, tt);
    if (nrow > 3) row_out<LL, 3>(pb, tt);
}

__global__ __launch_bounds__(512, 4)
void dct_layer_kernel(const float* __restrict__ x, float* __restrict__ out) {
    const int y0 = blockIdx.x * 4;   // 0,4,...,512
    const int kk = blockIdx.y;       // 0..3
    const int bc = blockIdx.z;       // 0..23
    const int t  = threadIdx.x;

    const float* __restrict__ xp = x + (size_t)bc * (HIN * WIN);

    // ---- staging: 7 rows x 128 float4 (predicated LDG.128)
#pragma unroll
    for (int s = 0; s < 2; s++) {
        const int idx = t + s * 512;
        if (idx < 7 * 128) {
            const int row = idx >> 7, j = idx & 127;
            const int iy = y0 - 2 + row;
            float4 v = make_float4(0.f, 0.f, 0.f, 0.f);
            if ((unsigned)iy < (unsigned)HIN)
                v = *reinterpret_cast<const float4*>(xp + iy * WIN + 4 * j);
            float* xr = &xin[row][2 + 4 * j];
            xr[0] = v.x; xr[1] = v.y; xr[2] = v.z; xr[3] = v.w;
        }
    }
    if (t < 7 * 8) {   // halo cols 0,1,514..519 per row
        const int row = t >> 3, q = t & 7;
        xin[row][(q < 2) ? q : (512 + q)] = 0.f;
    }
    __syncthreads();

    // ---- column pass for this kk only
    const float k0 = (kk == 0) ? 0.5f : (kk == 1) ? CA : (kk == 2) ? 0.5f : CB;
    const float k1 = (kk == 0) ? 0.5f : (kk == 1) ? CB : (kk == 2) ? -0.5f : -CA;
    const float k2 = (kk == 0) ? 0.5f : (kk == 1) ? -CB : (kk == 2) ? -0.5f : CA;
    const float k3 = (kk == 0) ? 0.5f : (kk == 1) ? -CA : (kk == 2) ? 0.5f : -CB;
    for (int c = t; c < XCOL; c += 512) {
        float v0 = xin[0][c], v1 = xin[1][c], v2 = xin[2][c], v3 = xin[3][c];
        float v4 = xin[4][c], v5 = xin[5][c], v6 = xin[6][c];
        sc[0][c] = fmaf(k0, v0, fmaf(k1, v1, fmaf(k2, v2, k3 * v3)));
        sc[1][c] = fmaf(k0, v1, fmaf(k1, v2, fmaf(k2, v3, k3 * v4)));
        sc[2][c] = fmaf(k0, v2, fmaf(k1, v3, fmaf(k2, v4, k3 * v5)));
        sc[3][c] = fmaf(k0, v3, fmaf(k1, v4, fmaf(k2, v5, k3 * v6)));
    }
    __syncthreads();

    // ---- row pass: ll-group writes its plane's 4-row contiguous strip
    const int ll = t >> 7, tt = t & 127;
    const int nrow = min(4, HOUT - y0);
    float* __restrict__ pb = out + (size_t)(bc * 16 + kk * 4 + ll) * PLANE
                                 + (size_t)y0 * WOUT + 4 * tt;
    switch (ll) {
        case 0: tail_ll<0>(pb, tt, nrow); break;
        case 1: tail_ll<1>(pb, tt, nrow); break;
        case 2: tail_ll<2>(pb, tt, nrow); break;
        default: tail_ll<3>(pb, tt, nrow); break;
    }
}

extern "C" void kernel_launch(void* const* d_in, const int* in_sizes, int n_in,
                              void* d_out, int out_size) {
    const float* x = (const float*)d_in[0];
    float* out     = (float*)d_out;
    (void)in_sizes; (void)n_in; (void)out_size;

    dim3 grid((HOUT + 3) / 4, 4, 8 * 3);   // (129, 4, 24)
    dim3 block(512);
    dct_layer_kernel<<<grid, block>>>(x, out);
}

// round 11
// speedup vs baseline: 1.1596x; 1.1391x over previous
#include <cuda_runtime.h>
#include <cstdint>

// DCT_Layer: grouped conv, fixed separable 4x4 DCT basis, pad=2, min(|v|,8).
// x: (8,3,512,512) f32 -> out: (8,48,513,513) f32
//
// Block = 512 threads = 4 groups of 128; group kk owns planes kk*4+ll.
// 4 output rows per block, y0 % 4 == 0 -> store shifts compile-time.
// Column pass reads input DIRECTLY from gmem (L2-resident), one barrier.
//   A[0]={.5,.5,.5,.5}; A[1]={a,b,-b,-a}; A[2]={.5,-.5,-.5,.5}; A[3]={b,-a,a,-b}

#define HIN   512
#define WIN   512
#define HOUT  513
#define WOUT  513
#define PLANE (HOUT * WOUT)   // 263169 (== 1 mod 4)
#define XCOL  520             // s-cols 0..519; input col = s-col - 2
#define CA 0.65328148243818826f
#define CB 0.27059805007309851f

__device__ __forceinline__ float t8(float v) { return fminf(fabsf(v), 8.0f); }

// 4-tap row DCT of window w at offset c (compile-time after unroll)
template<int LL>
__device__ __forceinline__ float rowdct(const float* __restrict__ w, int c) {
    if (LL == 0) return 0.5f * ((w[c] + w[c+1]) + (w[c+2] + w[c+3]));
    if (LL == 1) return CA * (w[c] - w[c+3]) + CB * (w[c+1] - w[c+2]);
    if (LL == 2) return 0.5f * ((w[c] + w[c+3]) - (w[c+1] + w[c+2]));
    return CB * (w[c] - w[c+3]) - CA * (w[c+1] - w[c+2]);
}

// One plane row: aligned float4 streaming store + edge columns.
// pl = plane base + y*513 + 4*tt; thread tt's window = s-cols 4tt..4tt+11.
template<int SH, int LL>
__device__ __forceinline__ void plane_out(const float* __restrict__ w,
                                          float* __restrict__ pl, int tt) {
    float4 v;
    v.x = t8(rowdct<LL>(w, SH + 0));
    v.y = t8(rowdct<LL>(w, SH + 1));
    v.z = t8(rowdct<LL>(w, SH + 2));
    v.w = t8(rowdct<LL>(w, SH + 3));
    if (SH <= 1 || tt < 127)
        __stcs(reinterpret_cast<float4*>(pl + SH), v);

    if (SH > 0 && tt == 0) {                 // left edge cols 0..SH-1
#pragma unroll
        for (int c = 0; c < SH; c++)
            pl[c] = t8(rowdct<LL>(w, c));
    }
    constexpr int NP = (WOUT - SH) >> 2;
    constexpr int RS = SH + 4 * NP;
    if (RS < WOUT && tt == 127) {            // right edge cols RS..512
#pragma unroll
        for (int c = RS; c < WOUT; c++)
            pl[c - 508] = t8(rowdct<LL>(w, c - 508));
    }
}

__shared__ float sc[16][XCOL];   // column DCT [kk*4+r][c]  (33,280 B)

// 4 planes of group kk for output row with (y % 4) == R; w = 12-col window
template<int R>
__device__ __forceinline__ void do_row(const float* __restrict__ w,
                                       float* __restrict__ pb, int tt) {
    plane_out<(4 - ((R + 0) & 3)) & 3, 0>(w, pb,                     tt);
    plane_out<(4 - ((R + 1) & 3)) & 3, 1>(w, pb + 1 * (size_t)PLANE, tt);
    plane_out<(4 - ((R + 2) & 3)) & 3, 2>(w, pb + 2 * (size_t)PLANE, tt);
    plane_out<(4 - ((R + 3) & 3)) & 3, 3>(w, pb + 3 * (size_t)PLANE, tt);
}

__global__ __launch_bounds__(512, 4)
void dct_layer_kernel(const float* __restrict__ x, float* __restrict__ out) {
    const int y0 = blockIdx.x * 4;   // 0,4,...,512
    const int bc = blockIdx.y;       // 0..23
    const int t  = threadIdx.x;

    const float* __restrict__ xp = x + (size_t)bc * (HIN * WIN);

    // ---- column pass, reading directly from gmem (coalesced, L2-resident)
    for (int c = t; c < XCOL; c += 512) {
        const int ix = c - 2;
        const bool cok = (unsigned)ix < (unsigned)WIN;
        float v[7];
#pragma unroll
        for (int i = 0; i < 7; i++) {
            const int iy = y0 - 2 + i;
            v[i] = (cok && (unsigned)iy < (unsigned)HIN)
                       ? __ldg(xp + iy * WIN + ix) : 0.0f;
        }
#pragma unroll
        for (int r = 0; r < 4; r++) {
            float a = v[r], b = v[r+1], d = v[r+2], e = v[r+3];
            float p = a + e, q = b + d;
            float m = a - e, n = b - d;
            sc[ 0 + r][c] = 0.5f * (p + q);
            sc[ 4 + r][c] = CA * m + CB * n;
            sc[ 8 + r][c] = 0.5f * (p - q);
            sc[12 + r][c] = CB * m - CA * n;
        }
    }
    __syncthreads();

    // ---- row pass: group kk = t>>7 handles planes kk*4 .. kk*4+3
    const int kk = t >> 7, tt = t & 127;
    float* __restrict__ pb = out + (size_t)(bc * 16 + kk * 4) * PLANE
                                 + (size_t)y0 * WOUT + 4 * tt;

#pragma unroll
    for (int r = 0; r < 4; r++) {
        if (y0 + r < HOUT) {
            float w[12];
            const float4* __restrict__ s4 =
                reinterpret_cast<const float4*>(&sc[kk * 4 + r][0]);
            float4 a = s4[tt], b = s4[tt + 1], c2 = s4[tt + 2];
            w[0] = a.x;  w[1] = a.y;  w[2]  = a.z;  w[3]  = a.w;
            w[4] = b.x;  w[5] = b.y;  w[6]  = b.z;  w[7]  = b.w;
            w[8] = c2.x; w[9] = c2.y; w[10] = c2.z; w[11] = c2.w;

            float* __restrict__ pr = pb + (size_t)r * WOUT;
            switch (r) {            // r literal under unroll; y%4 == r
                case 0: do_row<0>(w, pr, tt); break;
                case 1: do_row<1>(w, pr, tt); break;
                case 2: do_row<2>(w, pr, tt); break;
                default: do_row<3>(w, pr, tt); break;
            }
        }
    }
}

extern "C" void kernel_launch(void* const* d_in, const int* in_sizes, int n_in,
                              void* d_out, int out_size) {
    const float* x = (const float*)d_in[0];
    float* out     = (float*)d_out;
    (void)in_sizes; (void)n_in; (void)out_size;

    dim3 grid((HOUT + 3) / 4, 8 * 3);   // (129, 24)
    dim3 block(512);
    dct_layer_kernel<<<grid, block>>>(x, out);
}